// round 1
// baseline (speedup 1.0000x reference)
#include <cuda_runtime.h>

#define BB 4
#define TT 2048
#define CC 1024
#define HH 16
#define DD 64

// Scratch (device globals: allocation-free contract)
__device__ float g_Q[BB*HH*TT*DD];
__device__ float g_K[BB*HH*TT*DD];
__device__ float g_V[BB*HH*TT*DD];
__device__ float g_O[BB*TT*CC];

// ---------------------------------------------------------------------------
// QKV GEMM: X[8192,1024] @ W[1024,3072] + b  -> scatter to Q/K/V [B*H, T, D]
// ---------------------------------------------------------------------------
__global__ __launch_bounds__(256) void qkv_gemm_kernel(
    const float* __restrict__ X, const float* __restrict__ W,
    const float* __restrict__ bias)
{
    __shared__ float As[16][68];   // [k][m], padded
    __shared__ float Bs[16][64];   // [k][n]
    const int n0 = blockIdx.x << 6;
    const int m0 = blockIdx.y << 6;
    const int tid = threadIdx.x;
    const int tx = tid & 15, ty = tid >> 4;
    const int ar = tid >> 2,  ac4 = (tid & 3) << 2;
    const int br = tid >> 4,  bc4 = (tid & 15) << 2;

    float acc[4][4] = {};
    for (int k0 = 0; k0 < 1024; k0 += 16) {
        float4 av = *(const float4*)(X + (size_t)(m0 + ar) * 1024 + k0 + ac4);
        float4 bv = *(const float4*)(W + (size_t)(k0 + br) * 3072 + n0 + bc4);
        __syncthreads();
        As[ac4+0][ar] = av.x; As[ac4+1][ar] = av.y;
        As[ac4+2][ar] = av.z; As[ac4+3][ar] = av.w;
        *(float4*)&Bs[br][bc4] = bv;
        __syncthreads();
        #pragma unroll
        for (int kk = 0; kk < 16; kk++) {
            float4 a = *(const float4*)&As[kk][ty << 2];
            float4 b = *(const float4*)&Bs[kk][tx << 2];
            float aa[4] = {a.x, a.y, a.z, a.w};
            float bb[4] = {b.x, b.y, b.z, b.w};
            #pragma unroll
            for (int i = 0; i < 4; i++)
                #pragma unroll
                for (int j = 0; j < 4; j++)
                    acc[i][j] += aa[i] * bb[j];
        }
    }

    #pragma unroll
    for (int i = 0; i < 4; i++) {
        const int m = m0 + (ty << 2) + i;
        const int bi = m >> 11, t = m & 2047;
        #pragma unroll
        for (int j = 0; j < 4; j++) {
            const int col = n0 + (tx << 2) + j;
            const float v = acc[i][j] + bias[col];
            const int which = col >> 10;
            const int h = (col >> 6) & 15;
            const int d = col & 63;
            float* dst = (which == 0) ? g_Q : (which == 1) ? g_K : g_V;
            dst[(((size_t)(bi * HH + h)) * TT + t) * DD + d] = v;
        }
    }
}

// ---------------------------------------------------------------------------
// Flash attention, fp32. Grid: (T/64, B*H). 256 threads, BM=BN=64, D=64.
// Row reductions via shfl within 16-lane groups (row group = lanes [16k,16k+15]).
// ---------------------------------------------------------------------------
#define STR 68
__global__ __launch_bounds__(256) void attn_kernel()
{
    extern __shared__ float sm[];
    float* Qs  = sm;                 // [64][STR]
    float* KVs = sm + 64 * STR;      // [64][STR]  (K, then reused for V)
    float* Ps  = sm + 2 * 64 * STR;  // [64][STR]

    const int bh = blockIdx.y;
    const int q0 = blockIdx.x << 6;
    const float* Qp = g_Q + (size_t)bh * TT * DD;
    const float* Kp = g_K + (size_t)bh * TT * DD;
    const float* Vp = g_V + (size_t)bh * TT * DD;

    const int tid = threadIdx.x;
    const int tx = tid & 15, ty = tid >> 4;

    // Load Q tile (pre-scaled by 1/sqrt(D))
    for (int i = tid; i < 1024; i += 256) {
        int r = i >> 4, d4 = (i & 15) << 2;
        float4 v = *(const float4*)(Qp + (size_t)(q0 + r) * DD + d4);
        v.x *= 0.125f; v.y *= 0.125f; v.z *= 0.125f; v.w *= 0.125f;
        *(float4*)&Qs[r * STR + d4] = v;
    }

    float o[4][4] = {};
    float mrow[4], lrow[4];
    #pragma unroll
    for (int i = 0; i < 4; i++) { mrow[i] = -1e30f; lrow[i] = 0.f; }

    const int ntiles = blockIdx.x + 1;   // causal: only tiles with keys <= queries
    for (int kt = 0; kt < ntiles; kt++) {
        const int k0 = kt << 6;
        __syncthreads();   // previous tile's P@V reads done; also covers Q load
        for (int i = tid; i < 1024; i += 256) {
            int r = i >> 4, d4 = (i & 15) << 2;
            *(float4*)&KVs[r * STR + d4] =
                *(const float4*)(Kp + (size_t)(k0 + r) * DD + d4);
        }
        __syncthreads();

        // S = Q @ K^T  (4x4 per thread)
        float s[4][4] = {};
        #pragma unroll 2
        for (int d = 0; d < 64; d += 4) {
            float4 q[4], k[4];
            #pragma unroll
            for (int i = 0; i < 4; i++)
                q[i] = *(const float4*)&Qs[((ty << 2) + i) * STR + d];
            #pragma unroll
            for (int j = 0; j < 4; j++)
                k[j] = *(const float4*)&KVs[((tx << 2) + j) * STR + d];
            #pragma unroll
            for (int i = 0; i < 4; i++)
                #pragma unroll
                for (int j = 0; j < 4; j++)
                    s[i][j] += q[i].x * k[j].x + q[i].y * k[j].y
                             + q[i].z * k[j].z + q[i].w * k[j].w;
        }

        if (kt == blockIdx.x) {   // diagonal tile: causal mask
            #pragma unroll
            for (int i = 0; i < 4; i++)
                #pragma unroll
                for (int j = 0; j < 4; j++)
                    if (((tx << 2) + j) > ((ty << 2) + i)) s[i][j] = -1e30f;
        }

        // Online softmax update
        #pragma unroll
        for (int i = 0; i < 4; i++) {
            float mx = fmaxf(fmaxf(s[i][0], s[i][1]), fmaxf(s[i][2], s[i][3]));
            mx = fmaxf(mx, __shfl_xor_sync(0xffffffffu, mx, 1));
            mx = fmaxf(mx, __shfl_xor_sync(0xffffffffu, mx, 2));
            mx = fmaxf(mx, __shfl_xor_sync(0xffffffffu, mx, 4));
            mx = fmaxf(mx, __shfl_xor_sync(0xffffffffu, mx, 8));
            const float mnew = fmaxf(mrow[i], mx);
            const float alpha = __expf(mrow[i] - mnew);
            mrow[i] = mnew;
            float rs = 0.f;
            #pragma unroll
            for (int j = 0; j < 4; j++) {
                s[i][j] = __expf(s[i][j] - mnew);
                rs += s[i][j];
            }
            rs += __shfl_xor_sync(0xffffffffu, rs, 1);
            rs += __shfl_xor_sync(0xffffffffu, rs, 2);
            rs += __shfl_xor_sync(0xffffffffu, rs, 4);
            rs += __shfl_xor_sync(0xffffffffu, rs, 8);
            lrow[i] = lrow[i] * alpha + rs;
            #pragma unroll
            for (int j = 0; j < 4; j++) o[i][j] *= alpha;
            *(float4*)&Ps[((ty << 2) + i) * STR + (tx << 2)] =
                make_float4(s[i][0], s[i][1], s[i][2], s[i][3]);
        }
        __syncthreads();   // Ps written, K reads finished -> load V into KVs
        for (int i = tid; i < 1024; i += 256) {
            int r = i >> 4, d4 = (i & 15) << 2;
            *(float4*)&KVs[r * STR + d4] =
                *(const float4*)(Vp + (size_t)(k0 + r) * DD + d4);
        }
        __syncthreads();

        // O += P @ V
        #pragma unroll 2
        for (int k = 0; k < 64; k += 4) {
            float4 p[4], v[4];
            #pragma unroll
            for (int i = 0; i < 4; i++)
                p[i] = *(const float4*)&Ps[((ty << 2) + i) * STR + k];
            #pragma unroll
            for (int kk = 0; kk < 4; kk++)
                v[kk] = *(const float4*)&KVs[(k + kk) * STR + (tx << 2)];
            #pragma unroll
            for (int i = 0; i < 4; i++) {
                o[i][0] += p[i].x * v[0].x + p[i].y * v[1].x + p[i].z * v[2].x + p[i].w * v[3].x;
                o[i][1] += p[i].x * v[0].y + p[i].y * v[1].y + p[i].z * v[2].y + p[i].w * v[3].y;
                o[i][2] += p[i].x * v[0].z + p[i].y * v[1].z + p[i].z * v[2].z + p[i].w * v[3].z;
                o[i][3] += p[i].x * v[0].w + p[i].y * v[1].w + p[i].z * v[2].w + p[i].w * v[3].w;
            }
        }
    }

    // Epilogue: normalize, write O as [B, T, H*D] (= [B,T,C] for proj GEMM)
    const int bi = bh >> 4, h = bh & 15;
    #pragma unroll
    for (int i = 0; i < 4; i++) {
        const int trow = q0 + (ty << 2) + i;
        const float inv = 1.0f / lrow[i];
        float4 v = make_float4(o[i][0] * inv, o[i][1] * inv,
                               o[i][2] * inv, o[i][3] * inv);
        *(float4*)(g_O + ((size_t)(bi * TT + trow)) * CC + (h << 6) + (tx << 2)) = v;
    }
}

// ---------------------------------------------------------------------------
// Proj GEMM: O[8192,1024] @ W[1024,1024] + b -> out
// ---------------------------------------------------------------------------
__global__ __launch_bounds__(256) void proj_gemm_kernel(
    const float* __restrict__ W, const float* __restrict__ bias,
    float* __restrict__ out)
{
    __shared__ float As[16][68];
    __shared__ float Bs[16][64];
    const int n0 = blockIdx.x << 6;
    const int m0 = blockIdx.y << 6;
    const int tid = threadIdx.x;
    const int tx = tid & 15, ty = tid >> 4;
    const int ar = tid >> 2,  ac4 = (tid & 3) << 2;
    const int br = tid >> 4,  bc4 = (tid & 15) << 2;

    float acc[4][4] = {};
    for (int k0 = 0; k0 < 1024; k0 += 16) {
        float4 av = *(const float4*)(g_O + (size_t)(m0 + ar) * 1024 + k0 + ac4);
        float4 bv = *(const float4*)(W + (size_t)(k0 + br) * 1024 + n0 + bc4);
        __syncthreads();
        As[ac4+0][ar] = av.x; As[ac4+1][ar] = av.y;
        As[ac4+2][ar] = av.z; As[ac4+3][ar] = av.w;
        *(float4*)&Bs[br][bc4] = bv;
        __syncthreads();
        #pragma unroll
        for (int kk = 0; kk < 16; kk++) {
            float4 a = *(const float4*)&As[kk][ty << 2];
            float4 b = *(const float4*)&Bs[kk][tx << 2];
            float aa[4] = {a.x, a.y, a.z, a.w};
            float bb[4] = {b.x, b.y, b.z, b.w};
            #pragma unroll
            for (int i = 0; i < 4; i++)
                #pragma unroll
                for (int j = 0; j < 4; j++)
                    acc[i][j] += aa[i] * bb[j];
        }
    }

    #pragma unroll
    for (int i = 0; i < 4; i++) {
        const int m = m0 + (ty << 2) + i;
        #pragma unroll
        for (int j = 0; j < 4; j++) {
            const int col = n0 + (tx << 2) + j;
            out[(size_t)m * 1024 + col] = acc[i][j] + bias[col];
        }
    }
}

// ---------------------------------------------------------------------------
extern "C" void kernel_launch(void* const* d_in, const int* in_sizes, int n_in,
                              void* d_out, int out_size)
{
    (void)in_sizes; (void)n_in; (void)out_size;
    const float* x      = (const float*)d_in[0];
    const float* W_qkv  = (const float*)d_in[1];
    const float* b_qkv  = (const float*)d_in[2];
    const float* W_proj = (const float*)d_in[3];
    const float* b_proj = (const float*)d_in[4];
    float* out = (float*)d_out;

    static const int kAttnSmem = 3 * 64 * STR * sizeof(float);  // 52224 B
    cudaFuncSetAttribute(attn_kernel,
                         cudaFuncAttributeMaxDynamicSharedMemorySize, kAttnSmem);

    dim3 g1(3072 / 64, 8192 / 64);
    qkv_gemm_kernel<<<g1, 256>>>(x, W_qkv, b_qkv);

    dim3 g2(TT / 64, BB * HH);
    attn_kernel<<<g2, 256, kAttnSmem>>>();

    dim3 g3(1024 / 64, 8192 / 64);
    proj_gemm_kernel<<<g3, 256>>>(W_proj, b_proj, out);
}

// round 2
// speedup vs baseline: 3.2950x; 3.2950x over previous
#include <cuda_runtime.h>

#define BB 4
#define TT 2048
#define CC 1024
#define HH 16
#define DD 64

// Scratch (device globals: allocation-free contract)
__device__ float g_Q[BB*HH*TT*DD];
__device__ float g_K[BB*HH*TT*DD];
__device__ float g_V[BB*HH*TT*DD];
__device__ float g_O[BB*TT*CC];

__device__ __forceinline__ unsigned f2tf(float f) {
    unsigned u;
    asm("cvt.rna.tf32.f32 %0, %1;" : "=r"(u) : "f"(f));
    return u;
}

__device__ __forceinline__ void mma_tf32(float* d, const unsigned* a,
                                         const unsigned* b, const float* c) {
    asm volatile(
        "mma.sync.aligned.m16n8k8.row.col.f32.tf32.tf32.f32 "
        "{%0,%1,%2,%3}, {%4,%5,%6,%7}, {%8,%9}, {%10,%11,%12,%13};\n"
        : "=f"(d[0]), "=f"(d[1]), "=f"(d[2]), "=f"(d[3])
        : "r"(a[0]), "r"(a[1]), "r"(a[2]), "r"(a[3]),
          "r"(b[0]), "r"(b[1]),
          "f"(c[0]), "f"(c[1]), "f"(c[2]), "f"(c[3]));
}

#define LDV4(p) (*(const float4*)(p))

__device__ __forceinline__ uint4 cvt4(float4 v) {
    uint4 u;
    u.x = f2tf(v.x); u.y = f2tf(v.y); u.z = f2tf(v.z); u.w = f2tf(v.w);
    return u;
}

// ---------------------------------------------------------------------------
// TF32 GEMM skeleton: C[M,N] = A[M,K=1024] @ B[K,N] (+bias, custom epilogue)
// Block 128x128, BK=16, 256 threads, warp tile 64x32.
// ---------------------------------------------------------------------------
__device__ __forceinline__ void qkv_scatter(int m, int col, float v0, float v1) {
    const int bi = m >> 11, t = m & 2047;
    const int which = col >> 10;
    const int h = (col >> 6) & 15;
    const int d = col & 63;
    float* dst = (which == 0) ? g_Q : (which == 1) ? g_K : g_V;
    *(float2*)&dst[(((size_t)(bi * HH + h)) * TT + t) * DD + d] = make_float2(v0, v1);
}

__global__ __launch_bounds__(256, 2) void qkv_gemm_kernel(
    const float* __restrict__ A, const float* __restrict__ B,
    const float* __restrict__ bias)
{
    __shared__ unsigned As[128][20];   // [m][k]
    __shared__ unsigned Bs[16][136];   // [k][n]
    const int tid = threadIdx.x;
    const int warp = tid >> 5, lane = tid & 31;
    const int g = lane >> 2, cq = lane & 3;
    const int wm = (warp >> 2) * 64, wn = (warp & 3) * 32;
    const int m0 = blockIdx.y * 128, n0 = blockIdx.x * 128;
    const int am = tid >> 1, ak = (tid & 1) * 8;
    const int bk = tid >> 5;
    const int bn = lane * 4;

    const float* Ap = A + (size_t)(m0 + am) * 1024 + ak;
    const float* Bp = B + (size_t)bk * 3072 + n0 + bn;

    float4 ra0 = LDV4(Ap), ra1 = LDV4(Ap + 4);
    float4 rb0 = LDV4(Bp), rb1 = LDV4(Bp + 8 * 3072);

    float acc[4][4][4];
    #pragma unroll
    for (int i = 0; i < 4; i++)
        #pragma unroll
        for (int j = 0; j < 4; j++)
            #pragma unroll
            for (int r = 0; r < 4; r++) acc[i][j][r] = 0.f;

    for (int k0 = 0; k0 < 1024; k0 += 16) {
        __syncthreads();
        *(uint4*)&As[am][ak]     = cvt4(ra0);
        *(uint4*)&As[am][ak + 4] = cvt4(ra1);
        *(uint4*)&Bs[bk][bn]     = cvt4(rb0);
        *(uint4*)&Bs[bk + 8][bn] = cvt4(rb1);
        __syncthreads();
        if (k0 + 16 < 1024) {
            ra0 = LDV4(Ap + k0 + 16);
            ra1 = LDV4(Ap + k0 + 20);
            rb0 = LDV4(Bp + (size_t)(k0 + 16) * 3072);
            rb1 = LDV4(Bp + (size_t)(k0 + 24) * 3072);
        }
        #pragma unroll
        for (int kk = 0; kk < 16; kk += 8) {
            unsigned af[4][4], bf[4][2];
            #pragma unroll
            for (int mf = 0; mf < 4; mf++) {
                const int r = wm + 16 * mf + g;
                af[mf][0] = As[r][kk + cq];
                af[mf][1] = As[r + 8][kk + cq];
                af[mf][2] = As[r][kk + cq + 4];
                af[mf][3] = As[r + 8][kk + cq + 4];
            }
            #pragma unroll
            for (int nf = 0; nf < 4; nf++) {
                const int cn = wn + 8 * nf + g;
                bf[nf][0] = Bs[kk + cq][cn];
                bf[nf][1] = Bs[kk + cq + 4][cn];
            }
            #pragma unroll
            for (int mf = 0; mf < 4; mf++)
                #pragma unroll
                for (int nf = 0; nf < 4; nf++)
                    mma_tf32(acc[mf][nf], af[mf], bf[nf], acc[mf][nf]);
        }
    }

    #pragma unroll
    for (int mf = 0; mf < 4; mf++) {
        const int r0 = m0 + wm + 16 * mf + g;
        #pragma unroll
        for (int nf = 0; nf < 4; nf++) {
            const int col = n0 + wn + 8 * nf + 2 * cq;
            const float b0 = bias[col], b1 = bias[col + 1];
            qkv_scatter(r0,     col, acc[mf][nf][0] + b0, acc[mf][nf][1] + b1);
            qkv_scatter(r0 + 8, col, acc[mf][nf][2] + b0, acc[mf][nf][3] + b1);
        }
    }
}

__global__ __launch_bounds__(256, 2) void proj_gemm_kernel(
    const float* __restrict__ B, const float* __restrict__ bias,
    float* __restrict__ out)
{
    __shared__ unsigned As[128][20];
    __shared__ unsigned Bs[16][136];
    const int tid = threadIdx.x;
    const int warp = tid >> 5, lane = tid & 31;
    const int g = lane >> 2, cq = lane & 3;
    const int wm = (warp >> 2) * 64, wn = (warp & 3) * 32;
    const int m0 = blockIdx.y * 128, n0 = blockIdx.x * 128;
    const int am = tid >> 1, ak = (tid & 1) * 8;
    const int bk = tid >> 5;
    const int bn = lane * 4;

    const float* Ap = g_O + (size_t)(m0 + am) * 1024 + ak;
    const float* Bp = B + (size_t)bk * 1024 + n0 + bn;

    float4 ra0 = LDV4(Ap), ra1 = LDV4(Ap + 4);
    float4 rb0 = LDV4(Bp), rb1 = LDV4(Bp + 8 * 1024);

    float acc[4][4][4];
    #pragma unroll
    for (int i = 0; i < 4; i++)
        #pragma unroll
        for (int j = 0; j < 4; j++)
            #pragma unroll
            for (int r = 0; r < 4; r++) acc[i][j][r] = 0.f;

    for (int k0 = 0; k0 < 1024; k0 += 16) {
        __syncthreads();
        *(uint4*)&As[am][ak]     = cvt4(ra0);
        *(uint4*)&As[am][ak + 4] = cvt4(ra1);
        *(uint4*)&Bs[bk][bn]     = cvt4(rb0);
        *(uint4*)&Bs[bk + 8][bn] = cvt4(rb1);
        __syncthreads();
        if (k0 + 16 < 1024) {
            ra0 = LDV4(Ap + k0 + 16);
            ra1 = LDV4(Ap + k0 + 20);
            rb0 = LDV4(Bp + (size_t)(k0 + 16) * 1024);
            rb1 = LDV4(Bp + (size_t)(k0 + 24) * 1024);
        }
        #pragma unroll
        for (int kk = 0; kk < 16; kk += 8) {
            unsigned af[4][4], bf[4][2];
            #pragma unroll
            for (int mf = 0; mf < 4; mf++) {
                const int r = wm + 16 * mf + g;
                af[mf][0] = As[r][kk + cq];
                af[mf][1] = As[r + 8][kk + cq];
                af[mf][2] = As[r][kk + cq + 4];
                af[mf][3] = As[r + 8][kk + cq + 4];
            }
            #pragma unroll
            for (int nf = 0; nf < 4; nf++) {
                const int cn = wn + 8 * nf + g;
                bf[nf][0] = Bs[kk + cq][cn];
                bf[nf][1] = Bs[kk + cq + 4][cn];
            }
            #pragma unroll
            for (int mf = 0; mf < 4; mf++)
                #pragma unroll
                for (int nf = 0; nf < 4; nf++)
                    mma_tf32(acc[mf][nf], af[mf], bf[nf], acc[mf][nf]);
        }
    }

    #pragma unroll
    for (int mf = 0; mf < 4; mf++) {
        const int r0 = m0 + wm + 16 * mf + g;
        #pragma unroll
        for (int nf = 0; nf < 4; nf++) {
            const int col = n0 + wn + 8 * nf + 2 * cq;
            const float b0 = bias[col], b1 = bias[col + 1];
            *(float2*)&out[(size_t)r0 * 1024 + col] =
                make_float2(acc[mf][nf][0] + b0, acc[mf][nf][1] + b1);
            *(float2*)&out[(size_t)(r0 + 8) * 1024 + col] =
                make_float2(acc[mf][nf][2] + b0, acc[mf][nf][3] + b1);
        }
    }
}

// ---------------------------------------------------------------------------
// Tensor-core flash attention, tf32. Grid: (T/128, B*H). 256 thr, 8 warps.
// Warp tile 16(q) x 64(kv). Online softmax on C fragments.
// ---------------------------------------------------------------------------
#define QS_OFF 0
#define KS_OFF 8704
#define VS_OFF 13056
#define PS_OFF 17408
#define ATTN_SMEM_WORDS 26112

__global__ __launch_bounds__(256, 1) void attn_kernel()
{
    extern __shared__ unsigned sm[];
    unsigned* Qs = sm + QS_OFF;   // [128][68] tf32
    unsigned* Ks = sm + KS_OFF;   // [64][68]
    unsigned* Vs = sm + VS_OFF;   // [64][68]
    unsigned* Ps = sm + PS_OFF;   // [128][68]

    const int bh = blockIdx.y;
    const int qt = gridDim.x - 1 - blockIdx.x;   // heavy tiles first
    const int q0 = qt * 128;
    const float* Qp = g_Q + (size_t)bh * TT * DD;
    const float* Kp = g_K + (size_t)bh * TT * DD;
    const float* Vp = g_V + (size_t)bh * TT * DD;

    const int tid = threadIdx.x;
    const int warp = tid >> 5, lane = tid & 31;
    const int g = lane >> 2, cq = lane & 3;
    const int wm = warp * 16;

    // Load Q tile (scaled by 1/sqrt(D), converted to tf32)
    #pragma unroll
    for (int it = 0; it < 8; it++) {
        const int i = tid + it * 256;
        const int r = i >> 4, d4 = (i & 15) * 4;
        float4 v = LDV4(Qp + (size_t)(q0 + r) * DD + d4);
        v.x *= 0.125f; v.y *= 0.125f; v.z *= 0.125f; v.w *= 0.125f;
        *(uint4*)(Qs + r * 68 + d4) = cvt4(v);
    }

    float ofr[8][4];
    #pragma unroll
    for (int i = 0; i < 8; i++)
        #pragma unroll
        for (int j = 0; j < 4; j++) ofr[i][j] = 0.f;
    float m0r = -1e30f, m1r = -1e30f, l0r = 0.f, l1r = 0.f;

    const int row0 = q0 + wm + g;
    const int row1 = row0 + 8;
    const int ntiles = 2 * qt + 2;

    for (int kt = 0; kt < ntiles; kt++) {
        const int k0 = kt << 6;
        __syncthreads();   // prior tile reads done (covers Q load on kt=0)
        #pragma unroll
        for (int it = 0; it < 4; it++) {
            const int i = tid + it * 256;
            const int r = i >> 4, d4 = (i & 15) * 4;
            *(uint4*)(Ks + r * 68 + d4) = cvt4(LDV4(Kp + (size_t)(k0 + r) * DD + d4));
            *(uint4*)(Vs + r * 68 + d4) = cvt4(LDV4(Vp + (size_t)(k0 + r) * DD + d4));
        }
        __syncthreads();

        const bool active = (q0 + wm + 15) >= k0;   // warp-uniform
        if (active) {
            float sfr[8][4];
            #pragma unroll
            for (int i = 0; i < 8; i++)
                #pragma unroll
                for (int j = 0; j < 4; j++) sfr[i][j] = 0.f;

            #pragma unroll
            for (int kk = 0; kk < 64; kk += 8) {
                unsigned a[4];
                a[0] = Qs[(wm + g) * 68 + kk + cq];
                a[1] = Qs[(wm + g + 8) * 68 + kk + cq];
                a[2] = Qs[(wm + g) * 68 + kk + cq + 4];
                a[3] = Qs[(wm + g + 8) * 68 + kk + cq + 4];
                #pragma unroll
                for (int nf = 0; nf < 8; nf++) {
                    unsigned b[2];
                    b[0] = Ks[(8 * nf + g) * 68 + kk + cq];
                    b[1] = Ks[(8 * nf + g) * 68 + kk + cq + 4];
                    mma_tf32(sfr[nf], a, b, sfr[nf]);
                }
            }

            if (k0 + 63 > row0) {   // causal masking needed for some element
                #pragma unroll
                for (int nf = 0; nf < 8; nf++) {
                    const int col = k0 + 8 * nf + 2 * cq;
                    if (col > row0)     sfr[nf][0] = -1e30f;
                    if (col + 1 > row0) sfr[nf][1] = -1e30f;
                    if (col > row1)     sfr[nf][2] = -1e30f;
                    if (col + 1 > row1) sfr[nf][3] = -1e30f;
                }
            }

            // Online softmax, rows row0 (idx 0,1) and row1 (idx 2,3)
            float mx0 = -1e30f, mx1 = -1e30f;
            #pragma unroll
            for (int nf = 0; nf < 8; nf++) {
                mx0 = fmaxf(mx0, fmaxf(sfr[nf][0], sfr[nf][1]));
                mx1 = fmaxf(mx1, fmaxf(sfr[nf][2], sfr[nf][3]));
            }
            mx0 = fmaxf(mx0, __shfl_xor_sync(0xffffffffu, mx0, 1));
            mx0 = fmaxf(mx0, __shfl_xor_sync(0xffffffffu, mx0, 2));
            mx1 = fmaxf(mx1, __shfl_xor_sync(0xffffffffu, mx1, 1));
            mx1 = fmaxf(mx1, __shfl_xor_sync(0xffffffffu, mx1, 2));

            const float mn0 = fmaxf(m0r, mx0), mn1 = fmaxf(m1r, mx1);
            const float al0 = __expf(m0r - mn0), al1 = __expf(m1r - mn1);
            m0r = mn0; m1r = mn1;

            float rs0 = 0.f, rs1 = 0.f;
            #pragma unroll
            for (int nf = 0; nf < 8; nf++) {
                sfr[nf][0] = __expf(sfr[nf][0] - mn0);
                sfr[nf][1] = __expf(sfr[nf][1] - mn0);
                sfr[nf][2] = __expf(sfr[nf][2] - mn1);
                sfr[nf][3] = __expf(sfr[nf][3] - mn1);
                rs0 += sfr[nf][0] + sfr[nf][1];
                rs1 += sfr[nf][2] + sfr[nf][3];
            }
            rs0 += __shfl_xor_sync(0xffffffffu, rs0, 1);
            rs0 += __shfl_xor_sync(0xffffffffu, rs0, 2);
            rs1 += __shfl_xor_sync(0xffffffffu, rs1, 1);
            rs1 += __shfl_xor_sync(0xffffffffu, rs1, 2);
            l0r = l0r * al0 + rs0;
            l1r = l1r * al1 + rs1;

            #pragma unroll
            for (int df = 0; df < 8; df++) {
                ofr[df][0] *= al0; ofr[df][1] *= al0;
                ofr[df][2] *= al1; ofr[df][3] *= al1;
            }

            // Store P (tf32) to smem
            #pragma unroll
            for (int nf = 0; nf < 8; nf++) {
                uint2 u0 = make_uint2(f2tf(sfr[nf][0]), f2tf(sfr[nf][1]));
                uint2 u1 = make_uint2(f2tf(sfr[nf][2]), f2tf(sfr[nf][3]));
                *(uint2*)(Ps + (wm + g) * 68 + 8 * nf + 2 * cq) = u0;
                *(uint2*)(Ps + (wm + g + 8) * 68 + 8 * nf + 2 * cq) = u1;
            }
        }
        __syncwarp();
        if (active) {
            #pragma unroll
            for (int kk = 0; kk < 64; kk += 8) {
                unsigned a[4];
                a[0] = Ps[(wm + g) * 68 + kk + cq];
                a[1] = Ps[(wm + g + 8) * 68 + kk + cq];
                a[2] = Ps[(wm + g) * 68 + kk + cq + 4];
                a[3] = Ps[(wm + g + 8) * 68 + kk + cq + 4];
                #pragma unroll
                for (int df = 0; df < 8; df++) {
                    unsigned b[2];
                    b[0] = Vs[(kk + cq) * 68 + 8 * df + g];
                    b[1] = Vs[(kk + cq + 4) * 68 + 8 * df + g];
                    mma_tf32(ofr[df], a, b, ofr[df]);
                }
            }
        }
    }

    // Epilogue: normalize, write O as [B, T, C]
    const int bi = bh >> 4, h = bh & 15;
    const float il0 = 1.0f / l0r, il1 = 1.0f / l1r;
    float* ob0 = g_O + ((size_t)(bi * TT + row0)) * CC + (h << 6);
    float* ob1 = g_O + ((size_t)(bi * TT + row1)) * CC + (h << 6);
    #pragma unroll
    for (int df = 0; df < 8; df++) {
        const int col = 8 * df + 2 * cq;
        *(float2*)(ob0 + col) = make_float2(ofr[df][0] * il0, ofr[df][1] * il0);
        *(float2*)(ob1 + col) = make_float2(ofr[df][2] * il1, ofr[df][3] * il1);
    }
}

// ---------------------------------------------------------------------------
extern "C" void kernel_launch(void* const* d_in, const int* in_sizes, int n_in,
                              void* d_out, int out_size)
{
    (void)in_sizes; (void)n_in; (void)out_size;
    const float* x      = (const float*)d_in[0];
    const float* W_qkv  = (const float*)d_in[1];
    const float* b_qkv  = (const float*)d_in[2];
    const float* W_proj = (const float*)d_in[3];
    const float* b_proj = (const float*)d_in[4];
    float* out = (float*)d_out;

    static const int kAttnSmem = ATTN_SMEM_WORDS * 4;   // 104448 B
    cudaFuncSetAttribute(attn_kernel,
                         cudaFuncAttributeMaxDynamicSharedMemorySize, kAttnSmem);

    dim3 g1(3072 / 128, 8192 / 128);
    qkv_gemm_kernel<<<g1, 256>>>(x, W_qkv, b_qkv);

    dim3 g2(TT / 128, BB * HH);
    attn_kernel<<<g2, 256, kAttnSmem>>>();

    dim3 g3(1024 / 128, 8192 / 128);
    proj_gemm_kernel<<<g3, 256>>>(W_proj, b_proj, out);
}

// round 3
// speedup vs baseline: 3.8065x; 1.1552x over previous
#include <cuda_runtime.h>

#define BB 4
#define TT 2048
#define CC 1024
#define HH 16
#define DD 64
#define FULLMASK 0xffffffffu

// tf32 scratch (device globals: allocation-free contract)
__device__ unsigned g_Xt[BB*TT*CC];     // X as tf32
__device__ unsigned g_Wq[CC*3*CC];      // W_qkv as tf32
__device__ unsigned g_Wp[CC*CC];        // W_proj as tf32
__device__ unsigned g_Q[BB*HH*TT*DD];   // tf32, pre-scaled by 1/8
__device__ unsigned g_K[BB*HH*TT*DD];
__device__ unsigned g_V[BB*HH*TT*DD];
__device__ unsigned g_O[BB*TT*CC];      // attn output, tf32

__device__ __forceinline__ unsigned f2tf(float f) {
    unsigned u;
    asm("cvt.rna.tf32.f32 %0, %1;" : "=r"(u) : "f"(f));
    return u;
}

__device__ __forceinline__ void mma_tf32(float* d, const unsigned* a,
                                         const unsigned* b, const float* c) {
    asm volatile(
        "mma.sync.aligned.m16n8k8.row.col.f32.tf32.tf32.f32 "
        "{%0,%1,%2,%3}, {%4,%5,%6,%7}, {%8,%9}, {%10,%11,%12,%13};\n"
        : "=f"(d[0]), "=f"(d[1]), "=f"(d[2]), "=f"(d[3])
        : "r"(a[0]), "r"(a[1]), "r"(a[2]), "r"(a[3]),
          "r"(b[0]), "r"(b[1]),
          "f"(c[0]), "f"(c[1]), "f"(c[2]), "f"(c[3]));
}

__device__ __forceinline__ unsigned smaddr(const void* p) {
    return (unsigned)__cvta_generic_to_shared(p);
}
#define CPA16(dst, src) \
    asm volatile("cp.async.ca.shared.global [%0], [%1], 16;\n" :: "r"(dst), "l"(src))
#define CPCOMMIT() asm volatile("cp.async.commit_group;\n")
template<int N> __device__ __forceinline__ void cpwait() {
    asm volatile("cp.async.wait_group %0;\n" :: "n"(N));
}

__device__ __forceinline__ uint4 cvt4(float4 v) {
    uint4 u;
    u.x = f2tf(v.x); u.y = f2tf(v.y); u.z = f2tf(v.z); u.w = f2tf(v.w);
    return u;
}

// ---------------------------------------------------------------------------
// One-shot tf32 pre-conversion of X, W_qkv, W_proj (memory-bound, ~20us)
// ---------------------------------------------------------------------------
__global__ void cvt_kernel(const float* __restrict__ X,
                           const float* __restrict__ Wq,
                           const float* __restrict__ Wp)
{
    const int stride = gridDim.x * blockDim.x;
    const int i0 = blockIdx.x * blockDim.x + threadIdx.x;
    const float4* X4 = (const float4*)X;
    for (int i = i0; i < (BB*TT*CC)/4; i += stride) ((uint4*)g_Xt)[i] = cvt4(X4[i]);
    const float4* Wq4 = (const float4*)Wq;
    for (int i = i0; i < (CC*3*CC)/4; i += stride) ((uint4*)g_Wq)[i] = cvt4(Wq4[i]);
    const float4* Wp4 = (const float4*)Wp;
    for (int i = i0; i < (CC*CC)/4; i += stride) ((uint4*)g_Wp)[i] = cvt4(Wp4[i]);
}

// ---------------------------------------------------------------------------
// QKV GEMM: Xt[8192,1024] @ Wq[1024,3072] + b -> Q/K/V tf32 [B*H, T, D]
// 128x128 block, BK=16, 256 thr, warp 64x32, 2-stage cp.async pipeline.
// ---------------------------------------------------------------------------
__device__ __forceinline__ void qkv_scatter(int m, int col, float v0, float v1) {
    const int bi = m >> 11, t = m & 2047;
    const int which = col >> 10;
    const int h = (col >> 6) & 15;
    const int d = col & 63;
    unsigned* dst = (which == 0) ? g_Q : (which == 1) ? g_K : g_V;
    if (which == 0) { v0 *= 0.125f; v1 *= 0.125f; }   // fold 1/sqrt(D) into Q
    *(uint2*)&dst[(((size_t)(bi * HH + h)) * TT + t) * DD + d] =
        make_uint2(f2tf(v0), f2tf(v1));
}

__global__ __launch_bounds__(256, 2) void qkv_gemm_kernel(
    const float* __restrict__ bias)
{
    __shared__ unsigned As[2][128][20];   // [m][k]
    __shared__ unsigned Bs[2][16][136];   // [k][n]
    const int tid = threadIdx.x;
    const int warp = tid >> 5, lane = tid & 31;
    const int g = lane >> 2, cq = lane & 3;
    const int wm = (warp >> 2) * 64, wn = (warp & 3) * 32;
    const int m0 = blockIdx.y * 128, n0 = blockIdx.x * 128;
    const int am = tid >> 1, ak = (tid & 1) * 8;
    const int bk = tid >> 5;
    const int bn = lane * 4;

    const unsigned* Ap = g_Xt + (size_t)(m0 + am) * 1024 + ak;
    const unsigned* Bp = g_Wq + (size_t)bk * 3072 + n0 + bn;

    auto issue = [&](int k0, int s) {
        CPA16(smaddr(&As[s][am][ak]),     Ap + k0);
        CPA16(smaddr(&As[s][am][ak + 4]), Ap + k0 + 4);
        CPA16(smaddr(&Bs[s][bk][bn]),     Bp + (size_t)k0 * 3072);
        CPA16(smaddr(&Bs[s][bk + 8][bn]), Bp + (size_t)(k0 + 8) * 3072);
        CPCOMMIT();
    };
    issue(0, 0);

    float acc[4][4][4] = {};
    for (int k0 = 0; k0 < 1024; k0 += 16) {
        const int s = (k0 >> 4) & 1;
        if (k0 + 16 < 1024) { issue(k0 + 16, s ^ 1); cpwait<1>(); }
        else cpwait<0>();
        __syncthreads();
        #pragma unroll
        for (int kk = 0; kk < 16; kk += 8) {
            unsigned af[4][4], bf[4][2];
            #pragma unroll
            for (int mf = 0; mf < 4; mf++) {
                const int r = wm + 16 * mf + g;
                af[mf][0] = As[s][r][kk + cq];
                af[mf][1] = As[s][r + 8][kk + cq];
                af[mf][2] = As[s][r][kk + cq + 4];
                af[mf][3] = As[s][r + 8][kk + cq + 4];
            }
            #pragma unroll
            for (int nf = 0; nf < 4; nf++) {
                const int cn = wn + 8 * nf + g;
                bf[nf][0] = Bs[s][kk + cq][cn];
                bf[nf][1] = Bs[s][kk + cq + 4][cn];
            }
            #pragma unroll
            for (int mf = 0; mf < 4; mf++)
                #pragma unroll
                for (int nf = 0; nf < 4; nf++)
                    mma_tf32(acc[mf][nf], af[mf], bf[nf], acc[mf][nf]);
        }
        __syncthreads();
    }

    #pragma unroll
    for (int mf = 0; mf < 4; mf++) {
        const int r0 = m0 + wm + 16 * mf + g;
        #pragma unroll
        for (int nf = 0; nf < 4; nf++) {
            const int col = n0 + wn + 8 * nf + 2 * cq;
            const float b0 = bias[col], b1 = bias[col + 1];
            qkv_scatter(r0,     col, acc[mf][nf][0] + b0, acc[mf][nf][1] + b1);
            qkv_scatter(r0 + 8, col, acc[mf][nf][2] + b0, acc[mf][nf][3] + b1);
        }
    }
}

// ---------------------------------------------------------------------------
// Proj GEMM: O[8192,1024](tf32) @ Wp[1024,1024](tf32) + b -> out fp32
// ---------------------------------------------------------------------------
__global__ __launch_bounds__(256, 2) void proj_gemm_kernel(
    const float* __restrict__ bias, float* __restrict__ out)
{
    __shared__ unsigned As[2][128][20];
    __shared__ unsigned Bs[2][16][136];
    const int tid = threadIdx.x;
    const int warp = tid >> 5, lane = tid & 31;
    const int g = lane >> 2, cq = lane & 3;
    const int wm = (warp >> 2) * 64, wn = (warp & 3) * 32;
    const int m0 = blockIdx.y * 128, n0 = blockIdx.x * 128;
    const int am = tid >> 1, ak = (tid & 1) * 8;
    const int bk = tid >> 5;
    const int bn = lane * 4;

    const unsigned* Ap = g_O + (size_t)(m0 + am) * 1024 + ak;
    const unsigned* Bp = g_Wp + (size_t)bk * 1024 + n0 + bn;

    auto issue = [&](int k0, int s) {
        CPA16(smaddr(&As[s][am][ak]),     Ap + k0);
        CPA16(smaddr(&As[s][am][ak + 4]), Ap + k0 + 4);
        CPA16(smaddr(&Bs[s][bk][bn]),     Bp + (size_t)k0 * 1024);
        CPA16(smaddr(&Bs[s][bk + 8][bn]), Bp + (size_t)(k0 + 8) * 1024);
        CPCOMMIT();
    };
    issue(0, 0);

    float acc[4][4][4] = {};
    for (int k0 = 0; k0 < 1024; k0 += 16) {
        const int s = (k0 >> 4) & 1;
        if (k0 + 16 < 1024) { issue(k0 + 16, s ^ 1); cpwait<1>(); }
        else cpwait<0>();
        __syncthreads();
        #pragma unroll
        for (int kk = 0; kk < 16; kk += 8) {
            unsigned af[4][4], bf[4][2];
            #pragma unroll
            for (int mf = 0; mf < 4; mf++) {
                const int r = wm + 16 * mf + g;
                af[mf][0] = As[s][r][kk + cq];
                af[mf][1] = As[s][r + 8][kk + cq];
                af[mf][2] = As[s][r][kk + cq + 4];
                af[mf][3] = As[s][r + 8][kk + cq + 4];
            }
            #pragma unroll
            for (int nf = 0; nf < 4; nf++) {
                const int cn = wn + 8 * nf + g;
                bf[nf][0] = Bs[s][kk + cq][cn];
                bf[nf][1] = Bs[s][kk + cq + 4][cn];
            }
            #pragma unroll
            for (int mf = 0; mf < 4; mf++)
                #pragma unroll
                for (int nf = 0; nf < 4; nf++)
                    mma_tf32(acc[mf][nf], af[mf], bf[nf], acc[mf][nf]);
        }
        __syncthreads();
    }

    #pragma unroll
    for (int mf = 0; mf < 4; mf++) {
        const int r0 = m0 + wm + 16 * mf + g;
        #pragma unroll
        for (int nf = 0; nf < 4; nf++) {
            const int col = n0 + wn + 8 * nf + 2 * cq;
            const float b0 = bias[col], b1 = bias[col + 1];
            *(float2*)&out[(size_t)r0 * 1024 + col] =
                make_float2(acc[mf][nf][0] + b0, acc[mf][nf][1] + b1);
            *(float2*)&out[(size_t)(r0 + 8) * 1024 + col] =
                make_float2(acc[mf][nf][2] + b0, acc[mf][nf][3] + b1);
        }
    }
}

// ---------------------------------------------------------------------------
// Flash attention, tf32 tensor cores. Grid (T/128, B*H), 256 thr, 8 warps.
// Q in registers; K/V double-buffered via cp.async; P via warp shuffles.
// smem = 4 x [64][68] u32 = 69632 B -> 2 CTAs/SM.
// ---------------------------------------------------------------------------
#define KVW 4352   // words per 64x68 buffer

__global__ __launch_bounds__(256, 2) void attn_kernel()
{
    extern __shared__ unsigned sm[];   // [4*KVW]: stage0 {K,V}, stage1 {K,V}

    const int bh = blockIdx.y;
    const int qt = gridDim.x - 1 - blockIdx.x;   // heavy tiles first
    const int q0 = qt * 128;
    const unsigned* Qp = g_Q + (size_t)bh * TT * DD;
    const unsigned* Kp = g_K + (size_t)bh * TT * DD;
    const unsigned* Vp = g_V + (size_t)bh * TT * DD;

    const int tid = threadIdx.x;
    const int warp = tid >> 5, lane = tid & 31;
    const int g = lane >> 2, cq = lane & 3;
    const int wm = warp * 16;

    // --- Stage Q into stage1 region (overwritten from tile1 onward) ---
    unsigned* Qst = sm + 2 * KVW;
    #pragma unroll
    for (int it = 0; it < 8; it++) {
        const int i = tid + it * 256;          // 0..2047 (128 rows x 16 chunks)
        const int r = i >> 4, c4 = (i & 15) * 4;
        CPA16(smaddr(Qst + r * 68 + c4), Qp + (size_t)(q0 + r) * 64 + c4);
    }
    CPCOMMIT();

    auto issueKV = [&](int kt, int s) {
        unsigned* Kb = sm + s * 2 * KVW;
        unsigned* Vb = Kb + KVW;
        const int k0 = kt << 6;
        #pragma unroll
        for (int it = 0; it < 4; it++) {
            const int i = tid + it * 256;      // 0..1023 (64 rows x 16 chunks)
            const int r = i >> 4, c4 = (i & 15) * 4;
            CPA16(smaddr(Kb + r * 68 + c4), Kp + (size_t)(k0 + r) * 64 + c4);
            CPA16(smaddr(Vb + r * 68 + c4), Vp + (size_t)(k0 + r) * 64 + c4);
        }
        CPCOMMIT();
    };
    issueKV(0, 0);            // tile0 -> stage0 (in flight behind Q)

    cpwait<1>();              // Q arrived
    __syncthreads();
    unsigned qf[8][4];
    #pragma unroll
    for (int c = 0; c < 8; c++) {
        const int k = 8 * c;
        qf[c][0] = Qst[(wm + g) * 68 + k + cq];
        qf[c][1] = Qst[(wm + g + 8) * 68 + k + cq];
        qf[c][2] = Qst[(wm + g) * 68 + k + cq + 4];
        qf[c][3] = Qst[(wm + g + 8) * 68 + k + cq + 4];
    }
    __syncthreads();          // all warps done with Q region

    float ofr[8][4] = {};
    float m0r = -1e30f, m1r = -1e30f, l0r = 0.f, l1r = 0.f;
    const int row0 = q0 + wm + g;
    const int row1 = row0 + 8;
    const int ntiles = 2 * qt + 2;

    for (int kt = 0; kt < ntiles; kt++) {
        const int s = kt & 1;
        if (kt + 1 < ntiles) { issueKV(kt + 1, s ^ 1); cpwait<1>(); }
        else cpwait<0>();
        __syncthreads();
        unsigned* Ks = sm + s * 2 * KVW;
        unsigned* Vs = Ks + KVW;
        const int k0 = kt << 6;

        const bool active = (q0 + wm + 15) >= k0;   // warp-uniform
        if (active) {
            float sfr[8][4] = {};
            #pragma unroll
            for (int c = 0; c < 8; c++) {
                const int kk = 8 * c;
                #pragma unroll
                for (int nf = 0; nf < 8; nf++) {
                    unsigned b[2];
                    b[0] = Ks[(8 * nf + g) * 68 + kk + cq];
                    b[1] = Ks[(8 * nf + g) * 68 + kk + cq + 4];
                    mma_tf32(sfr[nf], qf[c], b, sfr[nf]);
                }
            }

            if (k0 + 63 > row0) {   // causal mask on diagonal tiles
                #pragma unroll
                for (int nf = 0; nf < 8; nf++) {
                    const int col = k0 + 8 * nf + 2 * cq;
                    if (col > row0)     sfr[nf][0] = -1e30f;
                    if (col + 1 > row0) sfr[nf][1] = -1e30f;
                    if (col > row1)     sfr[nf][2] = -1e30f;
                    if (col + 1 > row1) sfr[nf][3] = -1e30f;
                }
            }

            // Online softmax (rows row0: slots 0,1; row1: slots 2,3)
            float mx0 = -1e30f, mx1 = -1e30f;
            #pragma unroll
            for (int nf = 0; nf < 8; nf++) {
                mx0 = fmaxf(mx0, fmaxf(sfr[nf][0], sfr[nf][1]));
                mx1 = fmaxf(mx1, fmaxf(sfr[nf][2], sfr[nf][3]));
            }
            mx0 = fmaxf(mx0, __shfl_xor_sync(FULLMASK, mx0, 1));
            mx0 = fmaxf(mx0, __shfl_xor_sync(FULLMASK, mx0, 2));
            mx1 = fmaxf(mx1, __shfl_xor_sync(FULLMASK, mx1, 1));
            mx1 = fmaxf(mx1, __shfl_xor_sync(FULLMASK, mx1, 2));

            const float mn0 = fmaxf(m0r, mx0), mn1 = fmaxf(m1r, mx1);
            const float al0 = __expf(m0r - mn0), al1 = __expf(m1r - mn1);
            m0r = mn0; m1r = mn1;

            float rs0 = 0.f, rs1 = 0.f;
            #pragma unroll
            for (int nf = 0; nf < 8; nf++) {
                sfr[nf][0] = __expf(sfr[nf][0] - mn0);
                sfr[nf][1] = __expf(sfr[nf][1] - mn0);
                sfr[nf][2] = __expf(sfr[nf][2] - mn1);
                sfr[nf][3] = __expf(sfr[nf][3] - mn1);
                rs0 += sfr[nf][0] + sfr[nf][1];
                rs1 += sfr[nf][2] + sfr[nf][3];
            }
            rs0 += __shfl_xor_sync(FULLMASK, rs0, 1);
            rs0 += __shfl_xor_sync(FULLMASK, rs0, 2);
            rs1 += __shfl_xor_sync(FULLMASK, rs1, 1);
            rs1 += __shfl_xor_sync(FULLMASK, rs1, 2);
            l0r = l0r * al0 + rs0;
            l1r = l1r * al1 + rs1;

            #pragma unroll
            for (int df = 0; df < 8; df++) {
                ofr[df][0] *= al0; ofr[df][1] *= al0;
                ofr[df][2] *= al1; ofr[df][3] *= al1;
            }

            // P: C-fragment -> A-fragment via warp shuffles, then O += P @ V
            const int src1 = (lane & 28) | (cq >> 1);
            const int src2 = src1 + 2;
            #pragma unroll
            for (int nf = 0; nf < 8; nf++) {
                const float t0 = __shfl_sync(FULLMASK, sfr[nf][0], src1);
                const float t1 = __shfl_sync(FULLMASK, sfr[nf][1], src1);
                const float t2 = __shfl_sync(FULLMASK, sfr[nf][2], src1);
                const float t3 = __shfl_sync(FULLMASK, sfr[nf][3], src1);
                const float u0 = __shfl_sync(FULLMASK, sfr[nf][0], src2);
                const float u1 = __shfl_sync(FULLMASK, sfr[nf][1], src2);
                const float u2 = __shfl_sync(FULLMASK, sfr[nf][2], src2);
                const float u3 = __shfl_sync(FULLMASK, sfr[nf][3], src2);
                const bool odd = (cq & 1);
                unsigned pa[4];
                pa[0] = f2tf(odd ? t1 : t0);
                pa[1] = f2tf(odd ? t3 : t2);
                pa[2] = f2tf(odd ? u1 : u0);
                pa[3] = f2tf(odd ? u3 : u2);
                const int kk = 8 * nf;
                #pragma unroll
                for (int df = 0; df < 8; df++) {
                    unsigned b[2];
                    b[0] = Vs[(kk + cq) * 68 + 8 * df + g];
                    b[1] = Vs[(kk + cq + 4) * 68 + 8 * df + g];
                    mma_tf32(ofr[df], pa, b, ofr[df]);
                }
            }
        }
        __syncthreads();   // reads of stage s done before it is refilled
    }

    // Epilogue: normalize, write O (tf32) as [B, T, C]
    const int bi = bh >> 4, h = bh & 15;
    const float il0 = 1.0f / l0r, il1 = 1.0f / l1r;
    unsigned* ob0 = g_O + ((size_t)(bi * TT + row0)) * CC + (h << 6);
    unsigned* ob1 = g_O + ((size_t)(bi * TT + row1)) * CC + (h << 6);
    #pragma unroll
    for (int df = 0; df < 8; df++) {
        const int col = 8 * df + 2 * cq;
        *(uint2*)(ob0 + col) = make_uint2(f2tf(ofr[df][0] * il0), f2tf(ofr[df][1] * il0));
        *(uint2*)(ob1 + col) = make_uint2(f2tf(ofr[df][2] * il1), f2tf(ofr[df][3] * il1));
    }
}

// ---------------------------------------------------------------------------
extern "C" void kernel_launch(void* const* d_in, const int* in_sizes, int n_in,
                              void* d_out, int out_size)
{
    (void)in_sizes; (void)n_in; (void)out_size;
    const float* x      = (const float*)d_in[0];
    const float* W_qkv  = (const float*)d_in[1];
    const float* b_qkv  = (const float*)d_in[2];
    const float* W_proj = (const float*)d_in[3];
    const float* b_proj = (const float*)d_in[4];
    float* out = (float*)d_out;

    static const int kAttnSmem = 4 * KVW * 4;   // 69632 B
    cudaFuncSetAttribute(attn_kernel,
                         cudaFuncAttributeMaxDynamicSharedMemorySize, kAttnSmem);

    cvt_kernel<<<1184, 256>>>(x, W_qkv, W_proj);

    dim3 g1(3072 / 128, 8192 / 128);
    qkv_gemm_kernel<<<g1, 256>>>(b_qkv);

    dim3 g2(TT / 128, BB * HH);
    attn_kernel<<<g2, 256, kAttnSmem>>>();

    dim3 g3(1024 / 128, 8192 / 128);
    proj_gemm_kernel<<<g3, 256>>>(b_proj, out);
}

// round 4
// speedup vs baseline: 4.0160x; 1.0550x over previous
#include <cuda_runtime.h>

#define BB 4
#define TT 2048
#define CC 1024
#define HH 16
#define DD 64
#define FULLMASK 0xffffffffu

// tf32 scratch (device globals: allocation-free contract)
__device__ unsigned g_Xt[BB*TT*CC];     // X as tf32
__device__ unsigned g_Wq[CC*3*CC];      // W_qkv as tf32
__device__ unsigned g_Wp[CC*CC];        // W_proj as tf32
__device__ unsigned g_Q[BB*HH*TT*DD];   // tf32, pre-scaled by log2e/8
__device__ unsigned g_K[BB*HH*TT*DD];
__device__ unsigned g_V[BB*HH*TT*DD];
__device__ unsigned g_O[BB*TT*CC];      // attn output, tf32

__device__ __forceinline__ unsigned f2tf(float f) {
    unsigned u;
    asm("cvt.rna.tf32.f32 %0, %1;" : "=r"(u) : "f"(f));
    return u;
}
__device__ __forceinline__ float ex2f(float x) {
    float y;
    asm("ex2.approx.ftz.f32 %0, %1;" : "=f"(y) : "f"(x));
    return y;
}

__device__ __forceinline__ void mma_tf32(float* d, const unsigned* a,
                                         const unsigned* b, const float* c) {
    asm volatile(
        "mma.sync.aligned.m16n8k8.row.col.f32.tf32.tf32.f32 "
        "{%0,%1,%2,%3}, {%4,%5,%6,%7}, {%8,%9}, {%10,%11,%12,%13};\n"
        : "=f"(d[0]), "=f"(d[1]), "=f"(d[2]), "=f"(d[3])
        : "r"(a[0]), "r"(a[1]), "r"(a[2]), "r"(a[3]),
          "r"(b[0]), "r"(b[1]),
          "f"(c[0]), "f"(c[1]), "f"(c[2]), "f"(c[3]));
}

__device__ __forceinline__ unsigned smaddr(const void* p) {
    return (unsigned)__cvta_generic_to_shared(p);
}
#define CPA16(dst, src) \
    asm volatile("cp.async.cg.shared.global [%0], [%1], 16;\n" :: "r"(dst), "l"(src))
#define CPCOMMIT() asm volatile("cp.async.commit_group;\n")
template<int N> __device__ __forceinline__ void cpwait() {
    asm volatile("cp.async.wait_group %0;\n" :: "n"(N));
}

__device__ __forceinline__ uint4 cvt4(float4 v) {
    uint4 u;
    u.x = f2tf(v.x); u.y = f2tf(v.y); u.z = f2tf(v.z); u.w = f2tf(v.w);
    return u;
}

// ---------------------------------------------------------------------------
// One-shot tf32 pre-conversion of X, W_qkv, W_proj
// ---------------------------------------------------------------------------
__global__ void cvt_kernel(const float* __restrict__ X,
                           const float* __restrict__ Wq,
                           const float* __restrict__ Wp)
{
    const int stride = gridDim.x * blockDim.x;
    const int i0 = blockIdx.x * blockDim.x + threadIdx.x;
    const float4* X4 = (const float4*)X;
    for (int i = i0; i < (BB*TT*CC)/4; i += stride) ((uint4*)g_Xt)[i] = cvt4(X4[i]);
    const float4* Wq4 = (const float4*)Wq;
    for (int i = i0; i < (CC*3*CC)/4; i += stride) ((uint4*)g_Wq)[i] = cvt4(Wq4[i]);
    const float4* Wp4 = (const float4*)Wp;
    for (int i = i0; i < (CC*CC)/4; i += stride) ((uint4*)g_Wp)[i] = cvt4(Wp4[i]);
}

// ---------------------------------------------------------------------------
// QKV GEMM: Xt[8192,1024] @ Wq[1024,3072] + b -> Q/K/V tf32 [B*H, T, D]
// 128x128 block, BK=16, 256 thr, 3-stage cp.async, one sync per k-iter.
// ---------------------------------------------------------------------------
__device__ __forceinline__ void qkv_scatter(int m, int col, float v0, float v1) {
    const int bi = m >> 11, t = m & 2047;
    const int which = col >> 10;
    const int h = (col >> 6) & 15;
    const int d = col & 63;
    unsigned* dst = (which == 0) ? g_Q : (which == 1) ? g_K : g_V;
    if (which == 0) {                       // fold log2e/sqrt(D) into Q
        v0 *= 0.18033688f; v1 *= 0.18033688f;
    }
    *(uint2*)&dst[(((size_t)(bi * HH + h)) * TT + t) * DD + d] =
        make_uint2(f2tf(v0), f2tf(v1));
}

__global__ __launch_bounds__(256, 2) void qkv_gemm_kernel(
    const float* __restrict__ bias)
{
    __shared__ unsigned As[3][128][20];   // [m][k]
    __shared__ unsigned Bs[3][16][136];   // [k][n]
    const int tid = threadIdx.x;
    const int warp = tid >> 5, lane = tid & 31;
    const int g = lane >> 2, cq = lane & 3;
    const int wm = (warp >> 2) * 64, wn = (warp & 3) * 32;
    const int m0 = blockIdx.y * 128, n0 = blockIdx.x * 128;
    const int am = tid >> 1, ak = (tid & 1) * 8;
    const int bk = tid >> 5;
    const int bn = lane * 4;

    const unsigned* Ap = g_Xt + (size_t)(m0 + am) * 1024 + ak;
    const unsigned* Bp = g_Wq + (size_t)bk * 3072 + n0 + bn;

    auto issue = [&](int it, int s) {
        const int k0 = it << 4;
        CPA16(smaddr(&As[s][am][ak]),     Ap + k0);
        CPA16(smaddr(&As[s][am][ak + 4]), Ap + k0 + 4);
        CPA16(smaddr(&Bs[s][bk][bn]),     Bp + (size_t)k0 * 3072);
        CPA16(smaddr(&Bs[s][bk + 8][bn]), Bp + (size_t)(k0 + 8) * 3072);
        CPCOMMIT();
    };
    issue(0, 0); issue(1, 1);
    cpwait<1>();
    __syncthreads();

    float acc[4][4][4] = {};
    for (int it = 0; it < 64; it++) {
        const int s = it % 3;
        if (it + 2 < 64) issue(it + 2, (it + 2) % 3);

        unsigned af[2][4][4];
        #pragma unroll
        for (int h = 0; h < 2; h++) {
            const int kk = h * 8;
            #pragma unroll
            for (int mf = 0; mf < 4; mf++) {
                const int r = wm + 16 * mf + g;
                af[h][mf][0] = As[s][r][kk + cq];
                af[h][mf][1] = As[s][r + 8][kk + cq];
                af[h][mf][2] = As[s][r][kk + cq + 4];
                af[h][mf][3] = As[s][r + 8][kk + cq + 4];
            }
        }
        unsigned bf[4][2];
        #pragma unroll
        for (int nf = 0; nf < 4; nf++) {
            const int cn = wn + 8 * nf + g;
            bf[nf][0] = Bs[s][cq][cn];
            bf[nf][1] = Bs[s][cq + 4][cn];
        }
        #pragma unroll
        for (int mf = 0; mf < 4; mf++)
            #pragma unroll
            for (int nf = 0; nf < 4; nf++)
                mma_tf32(acc[mf][nf], af[0][mf], bf[nf], acc[mf][nf]);
        #pragma unroll
        for (int nf = 0; nf < 4; nf++) {
            const int cn = wn + 8 * nf + g;
            bf[nf][0] = Bs[s][8 + cq][cn];
            bf[nf][1] = Bs[s][8 + cq + 4][cn];
        }
        #pragma unroll
        for (int mf = 0; mf < 4; mf++)
            #pragma unroll
            for (int nf = 0; nf < 4; nf++)
                mma_tf32(acc[mf][nf], af[1][mf], bf[nf], acc[mf][nf]);

        if (it + 1 < 64) {
            if (it + 2 < 64) cpwait<1>(); else cpwait<0>();
            __syncthreads();
        }
    }

    #pragma unroll
    for (int mf = 0; mf < 4; mf++) {
        const int r0 = m0 + wm + 16 * mf + g;
        #pragma unroll
        for (int nf = 0; nf < 4; nf++) {
            const int col = n0 + wn + 8 * nf + 2 * cq;
            const float b0 = bias[col], b1 = bias[col + 1];
            qkv_scatter(r0,     col, acc[mf][nf][0] + b0, acc[mf][nf][1] + b1);
            qkv_scatter(r0 + 8, col, acc[mf][nf][2] + b0, acc[mf][nf][3] + b1);
        }
    }
}

// ---------------------------------------------------------------------------
// Proj GEMM: O[8192,1024](tf32) @ Wp[1024,1024](tf32) + b -> out fp32
// ---------------------------------------------------------------------------
__global__ __launch_bounds__(256, 2) void proj_gemm_kernel(
    const float* __restrict__ bias, float* __restrict__ out)
{
    __shared__ unsigned As[3][128][20];
    __shared__ unsigned Bs[3][16][136];
    const int tid = threadIdx.x;
    const int warp = tid >> 5, lane = tid & 31;
    const int g = lane >> 2, cq = lane & 3;
    const int wm = (warp >> 2) * 64, wn = (warp & 3) * 32;
    const int m0 = blockIdx.y * 128, n0 = blockIdx.x * 128;
    const int am = tid >> 1, ak = (tid & 1) * 8;
    const int bk = tid >> 5;
    const int bn = lane * 4;

    const unsigned* Ap = g_O + (size_t)(m0 + am) * 1024 + ak;
    const unsigned* Bp = g_Wp + (size_t)bk * 1024 + n0 + bn;

    auto issue = [&](int it, int s) {
        const int k0 = it << 4;
        CPA16(smaddr(&As[s][am][ak]),     Ap + k0);
        CPA16(smaddr(&As[s][am][ak + 4]), Ap + k0 + 4);
        CPA16(smaddr(&Bs[s][bk][bn]),     Bp + (size_t)k0 * 1024);
        CPA16(smaddr(&Bs[s][bk + 8][bn]), Bp + (size_t)(k0 + 8) * 1024);
        CPCOMMIT();
    };
    issue(0, 0); issue(1, 1);
    cpwait<1>();
    __syncthreads();

    float acc[4][4][4] = {};
    for (int it = 0; it < 64; it++) {
        const int s = it % 3;
        if (it + 2 < 64) issue(it + 2, (it + 2) % 3);

        unsigned af[2][4][4];
        #pragma unroll
        for (int h = 0; h < 2; h++) {
            const int kk = h * 8;
            #pragma unroll
            for (int mf = 0; mf < 4; mf++) {
                const int r = wm + 16 * mf + g;
                af[h][mf][0] = As[s][r][kk + cq];
                af[h][mf][1] = As[s][r + 8][kk + cq];
                af[h][mf][2] = As[s][r][kk + cq + 4];
                af[h][mf][3] = As[s][r + 8][kk + cq + 4];
            }
        }
        unsigned bf[4][2];
        #pragma unroll
        for (int nf = 0; nf < 4; nf++) {
            const int cn = wn + 8 * nf + g;
            bf[nf][0] = Bs[s][cq][cn];
            bf[nf][1] = Bs[s][cq + 4][cn];
        }
        #pragma unroll
        for (int mf = 0; mf < 4; mf++)
            #pragma unroll
            for (int nf = 0; nf < 4; nf++)
                mma_tf32(acc[mf][nf], af[0][mf], bf[nf], acc[mf][nf]);
        #pragma unroll
        for (int nf = 0; nf < 4; nf++) {
            const int cn = wn + 8 * nf + g;
            bf[nf][0] = Bs[s][8 + cq][cn];
            bf[nf][1] = Bs[s][8 + cq + 4][cn];
        }
        #pragma unroll
        for (int mf = 0; mf < 4; mf++)
            #pragma unroll
            for (int nf = 0; nf < 4; nf++)
                mma_tf32(acc[mf][nf], af[1][mf], bf[nf], acc[mf][nf]);

        if (it + 1 < 64) {
            if (it + 2 < 64) cpwait<1>(); else cpwait<0>();
            __syncthreads();
        }
    }

    #pragma unroll
    for (int mf = 0; mf < 4; mf++) {
        const int r0 = m0 + wm + 16 * mf + g;
        #pragma unroll
        for (int nf = 0; nf < 4; nf++) {
            const int col = n0 + wn + 8 * nf + 2 * cq;
            const float b0 = bias[col], b1 = bias[col + 1];
            *(float2*)&out[(size_t)r0 * 1024 + col] =
                make_float2(acc[mf][nf][0] + b0, acc[mf][nf][1] + b1);
            *(float2*)&out[(size_t)(r0 + 8) * 1024 + col] =
                make_float2(acc[mf][nf][2] + b0, acc[mf][nf][3] + b1);
        }
    }
}

// ---------------------------------------------------------------------------
// Flash attention, tf32. Grid (T/128, B*H), 256 thr, 8 warps.
// Q in registers; K/V 3-stage cp.async, one sync per tile; softmax in exp2.
// smem = 6 x [64][68] u32 = 104448 B -> 2 CTAs/SM.
// ---------------------------------------------------------------------------
#define KVW 4352   // words per 64x68 buffer

__global__ __launch_bounds__(256, 2) void attn_kernel()
{
    extern __shared__ unsigned sm[];   // stages 0..2, each {K,V} of KVW words

    const int bh = blockIdx.y;
    const int qt = gridDim.x - 1 - blockIdx.x;   // heavy tiles first
    const int q0 = qt * 128;
    const unsigned* Qp = g_Q + (size_t)bh * TT * DD;
    const unsigned* Kp = g_K + (size_t)bh * TT * DD;
    const unsigned* Vp = g_V + (size_t)bh * TT * DD;

    const int tid = threadIdx.x;
    const int warp = tid >> 5, lane = tid & 31;
    const int g = lane >> 2, cq = lane & 3;
    const int wm = warp * 16;

    // --- Stage Q into stage-2 region (reused for KV from tile 2 onward) ---
    unsigned* Qst = sm + 4 * KVW;
    #pragma unroll
    for (int it = 0; it < 8; it++) {
        const int i = tid + it * 256;          // 128 rows x 16 chunks
        const int r = i >> 4, c4 = (i & 15) * 4;
        CPA16(smaddr(Qst + r * 68 + c4), Qp + (size_t)(q0 + r) * 64 + c4);
    }
    CPCOMMIT();

    auto issueKV = [&](int kt, int s) {
        unsigned* Kb = sm + s * 2 * KVW;
        unsigned* Vb = Kb + KVW;
        const int k0 = kt << 6;
        #pragma unroll
        for (int it = 0; it < 4; it++) {
            const int i = tid + it * 256;      // 64 rows x 16 chunks
            const int r = i >> 4, c4 = (i & 15) * 4;
            CPA16(smaddr(Kb + r * 68 + c4), Kp + (size_t)(k0 + r) * 64 + c4);
            CPA16(smaddr(Vb + r * 68 + c4), Vp + (size_t)(k0 + r) * 64 + c4);
        }
        CPCOMMIT();
    };
    const int ntiles = 2 * qt + 2;
    issueKV(0, 0);
    issueKV(1, 1);

    cpwait<2>();              // Q arrived
    __syncthreads();
    unsigned qf[8][4];
    #pragma unroll
    for (int c = 0; c < 8; c++) {
        const int k = 8 * c;
        qf[c][0] = Qst[(wm + g) * 68 + k + cq];
        qf[c][1] = Qst[(wm + g + 8) * 68 + k + cq];
        qf[c][2] = Qst[(wm + g) * 68 + k + cq + 4];
        qf[c][3] = Qst[(wm + g + 8) * 68 + k + cq + 4];
    }
    cpwait<1>();              // tile0 KV arrived
    __syncthreads();          // Q region free + tile0 visible

    float ofr[8][4] = {};
    float m0r = -1e30f, m1r = -1e30f, l0r = 0.f, l1r = 0.f;
    const int row0 = q0 + wm + g;
    const int row1 = row0 + 8;

    for (int kt = 0; kt < ntiles; kt++) {
        const int s = kt % 3;
        if (kt + 2 < ntiles) issueKV(kt + 2, (kt + 2) % 3);
        unsigned* Ks = sm + s * 2 * KVW;
        unsigned* Vs = Ks + KVW;
        const int k0 = kt << 6;

        const bool active = (q0 + wm + 15) >= k0;   // warp-uniform
        if (active) {
            float sfr[8][4] = {};
            #pragma unroll
            for (int c = 0; c < 8; c++) {
                const int kk = 8 * c;
                #pragma unroll
                for (int nf = 0; nf < 8; nf++) {
                    unsigned b[2];
                    b[0] = Ks[(8 * nf + g) * 68 + kk + cq];
                    b[1] = Ks[(8 * nf + g) * 68 + kk + cq + 4];
                    mma_tf32(sfr[nf], qf[c], b, sfr[nf]);
                }
            }

            if (k0 + 63 > row0) {   // causal mask on diagonal tiles
                #pragma unroll
                for (int nf = 0; nf < 8; nf++) {
                    const int col = k0 + 8 * nf + 2 * cq;
                    if (col > row0)     sfr[nf][0] = -1e30f;
                    if (col + 1 > row0) sfr[nf][1] = -1e30f;
                    if (col > row1)     sfr[nf][2] = -1e30f;
                    if (col + 1 > row1) sfr[nf][3] = -1e30f;
                }
            }

            // Online softmax in base-2 (rows row0: slots 0,1; row1: 2,3)
            float mx0 = -1e30f, mx1 = -1e30f;
            #pragma unroll
            for (int nf = 0; nf < 8; nf++) {
                mx0 = fmaxf(mx0, fmaxf(sfr[nf][0], sfr[nf][1]));
                mx1 = fmaxf(mx1, fmaxf(sfr[nf][2], sfr[nf][3]));
            }
            mx0 = fmaxf(mx0, __shfl_xor_sync(FULLMASK, mx0, 1));
            mx0 = fmaxf(mx0, __shfl_xor_sync(FULLMASK, mx0, 2));
            mx1 = fmaxf(mx1, __shfl_xor_sync(FULLMASK, mx1, 1));
            mx1 = fmaxf(mx1, __shfl_xor_sync(FULLMASK, mx1, 2));

            const float mn0 = fmaxf(m0r, mx0), mn1 = fmaxf(m1r, mx1);
            const float al0 = ex2f(m0r - mn0), al1 = ex2f(m1r - mn1);
            m0r = mn0; m1r = mn1;

            float rs0 = 0.f, rs1 = 0.f;
            #pragma unroll
            for (int nf = 0; nf < 8; nf++) {
                sfr[nf][0] = ex2f(sfr[nf][0] - mn0);
                sfr[nf][1] = ex2f(sfr[nf][1] - mn0);
                sfr[nf][2] = ex2f(sfr[nf][2] - mn1);
                sfr[nf][3] = ex2f(sfr[nf][3] - mn1);
                rs0 += sfr[nf][0] + sfr[nf][1];
                rs1 += sfr[nf][2] + sfr[nf][3];
            }
            rs0 += __shfl_xor_sync(FULLMASK, rs0, 1);
            rs0 += __shfl_xor_sync(FULLMASK, rs0, 2);
            rs1 += __shfl_xor_sync(FULLMASK, rs1, 1);
            rs1 += __shfl_xor_sync(FULLMASK, rs1, 2);
            l0r = l0r * al0 + rs0;
            l1r = l1r * al1 + rs1;

            #pragma unroll
            for (int df = 0; df < 8; df++) {
                ofr[df][0] *= al0; ofr[df][1] *= al0;
                ofr[df][2] *= al1; ofr[df][3] *= al1;
            }

            // P: C-fragment -> A-fragment via warp shuffles, then O += P @ V
            const int src1 = (lane & 28) | (cq >> 1);
            const int src2 = src1 + 2;
            #pragma unroll
            for (int nf = 0; nf < 8; nf++) {
                const float t0 = __shfl_sync(FULLMASK, sfr[nf][0], src1);
                const float t1 = __shfl_sync(FULLMASK, sfr[nf][1], src1);
                const float t2 = __shfl_sync(FULLMASK, sfr[nf][2], src1);
                const float t3 = __shfl_sync(FULLMASK, sfr[nf][3], src1);
                const float u0 = __shfl_sync(FULLMASK, sfr[nf][0], src2);
                const float u1 = __shfl_sync(FULLMASK, sfr[nf][1], src2);
                const float u2 = __shfl_sync(FULLMASK, sfr[nf][2], src2);
                const float u3 = __shfl_sync(FULLMASK, sfr[nf][3], src2);
                const bool odd = (cq & 1);
                unsigned pa[4];
                pa[0] = f2tf(odd ? t1 : t0);
                pa[1] = f2tf(odd ? t3 : t2);
                pa[2] = f2tf(odd ? u1 : u0);
                pa[3] = f2tf(odd ? u3 : u2);
                const int kk = 8 * nf;
                #pragma unroll
                for (int df = 0; df < 8; df++) {
                    unsigned b[2];
                    b[0] = Vs[(kk + cq) * 68 + 8 * df + g];
                    b[1] = Vs[(kk + cq + 4) * 68 + 8 * df + g];
                    mma_tf32(ofr[df], pa, b, ofr[df]);
                }
            }
        }
        if (kt + 1 < ntiles) {
            if (kt + 2 < ntiles) cpwait<1>(); else cpwait<0>();
            __syncthreads();   // next tile visible + this stage read-complete
        }
    }

    // Epilogue: normalize, write O (tf32) as [B, T, C]
    const int bi = bh >> 4, h = bh & 15;
    const float il0 = 1.0f / l0r, il1 = 1.0f / l1r;
    unsigned* ob0 = g_O + ((size_t)(bi * TT + row0)) * CC + (h << 6);
    unsigned* ob1 = g_O + ((size_t)(bi * TT + row1)) * CC + (h << 6);
    #pragma unroll
    for (int df = 0; df < 8; df++) {
        const int col = 8 * df + 2 * cq;
        *(uint2*)(ob0 + col) = make_uint2(f2tf(ofr[df][0] * il0), f2tf(ofr[df][1] * il0));
        *(uint2*)(ob1 + col) = make_uint2(f2tf(ofr[df][2] * il1), f2tf(ofr[df][3] * il1));
    }
}

// ---------------------------------------------------------------------------
extern "C" void kernel_launch(void* const* d_in, const int* in_sizes, int n_in,
                              void* d_out, int out_size)
{
    (void)in_sizes; (void)n_in; (void)out_size;
    const float* x      = (const float*)d_in[0];
    const float* W_qkv  = (const float*)d_in[1];
    const float* b_qkv  = (const float*)d_in[2];
    const float* W_proj = (const float*)d_in[3];
    const float* b_proj = (const float*)d_in[4];
    float* out = (float*)d_out;

    static const int kAttnSmem = 6 * KVW * 4;   // 104448 B
    cudaFuncSetAttribute(attn_kernel,
                         cudaFuncAttributeMaxDynamicSharedMemorySize, kAttnSmem);

    cvt_kernel<<<1184, 256>>>(x, W_qkv, W_proj);

    dim3 g1(3072 / 128, 8192 / 128);
    qkv_gemm_kernel<<<g1, 256>>>(b_qkv);

    dim3 g2(TT / 128, BB * HH);
    attn_kernel<<<g2, 256, kAttnSmem>>>();

    dim3 g3(1024 / 128, 8192 / 128);
    proj_gemm_kernel<<<g3, 256>>>(b_proj, out);
}